// round 10
// baseline (speedup 1.0000x reference)
#include <cuda_runtime.h>
#include <cuda_bf16.h>
#include <cstdint>

// Problem constants (fixed shapes for this problem)
#define N_NODES 50000
#define D_IN    128
#define D_FF    256
#define D_OUT   119

// Scratch (allocation-free rule: __device__ globals). 16B-aligned.
__device__ __align__(16) float g_h[(size_t)N_NODES * D_IN];      // 25.6 MB
__device__ __align__(16) float g_aggr[(size_t)N_NODES * D_IN];   // 25.6 MB
__device__ __align__(16) float g_hid[(size_t)N_NODES * D_FF];    // 51.2 MB
__device__ unsigned g_maskbits[(N_NODES + 31) / 32];             // 6.25 KB

// ---------------------------------------------------------------------------
// MMA + ldmatrix primitives
// ---------------------------------------------------------------------------
__device__ __forceinline__ void mma16816(float* c, const uint32_t* a,
                                         uint32_t b0, uint32_t b1)
{
    asm volatile(
        "mma.sync.aligned.m16n8k16.row.col.f32.bf16.bf16.f32 "
        "{%0,%1,%2,%3}, {%4,%5,%6,%7}, {%8,%9}, {%0,%1,%2,%3};"
        : "+f"(c[0]), "+f"(c[1]), "+f"(c[2]), "+f"(c[3])
        : "r"(a[0]), "r"(a[1]), "r"(a[2]), "r"(a[3]), "r"(b0), "r"(b1));
}

__device__ __forceinline__ void ldsm4(uint32_t* r, const uint32_t* p)
{
    uint32_t a = (uint32_t)__cvta_generic_to_shared(p);
    asm volatile("ldmatrix.sync.aligned.m8n8.x4.shared.b16 {%0,%1,%2,%3}, [%4];"
                 : "=r"(r[0]), "=r"(r[1]), "=r"(r[2]), "=r"(r[3]) : "r"(a));
}

__device__ __forceinline__ void split_bf16(float x, __nv_bfloat16& hi, __nv_bfloat16& lo)
{
    hi = __float2bfloat16_rn(x);
    lo = __float2bfloat16_rn(x - __bfloat162float(hi));
}

// Convert a float4 into hi/lo bf16x2 pair words
__device__ __forceinline__ void cvt4(const float4& v, uint32_t& h0, uint32_t& h1,
                                     uint32_t& l0, uint32_t& l1)
{
    __nv_bfloat16 hx, lx, hy, ly, hz, lz, hw, lw;
    split_bf16(v.x, hx, lx); split_bf16(v.y, hy, ly);
    split_bf16(v.z, hz, lz); split_bf16(v.w, hw, lw);
    __nv_bfloat162 a = __nv_bfloat162(hx, hy), b = __nv_bfloat162(hz, hw);
    __nv_bfloat162 c = __nv_bfloat162(lx, ly), d = __nv_bfloat162(lz, lw);
    h0 = *(uint32_t*)&a; h1 = *(uint32_t*)&b;
    l0 = *(uint32_t*)&c; l1 = *(uint32_t*)&d;
}

// ---------------------------------------------------------------------------
// bf16-split tensor-core GEMM, 2-stage pipeline, occupancy-tuned.
// C[M,P] = act( op(A)[M,K] @ B[P,K]^T + bias )
// acc += Ah*Bh + Al*Bh + Ah*Bl  (fp32 accumulate; error ~1e-5)
// BM=64, BN=64, BK=32; 256 threads = 8 warps (2x4); warp tile 32x16.
// smem 40KB/CTA, target 3 CTAs/SM (reg-capped via launch_bounds).
// ---------------------------------------------------------------------------
#define BMg 64
#define BNg 64
#define ASP 20   /* smem stride in bf16 PAIRS (40 bf16 = 80B) */
#define BSP 20
#define SMEM_WORDS (4 * BMg * ASP + 4 * BNg * BSP)   /* 10240 words = 40960 B */

template<bool PRELU_A, bool RELU_OUT, bool HAS_BIAS, bool FUSED_MS>
__global__ __launch_bounds__(256, 3)
void gemm_mma_kernel(const float* __restrict__ A, const float* __restrict__ B,
                     const float* __restrict__ bias, float* __restrict__ C,
                     float* __restrict__ C2,
                     int M, int K, int P, const float* __restrict__ prelu_a,
                     const float* __restrict__ emb1, const float* __restrict__ emb2)
{
    extern __shared__ uint32_t smem[];
    uint32_t* AH = smem;                             // [2][BMg*ASP]
    uint32_t* AL = smem + 2 * BMg * ASP;
    uint32_t* BH = smem + 4 * BMg * ASP;             // [2][BNg*BSP]
    uint32_t* BL = smem + 4 * BMg * ASP + 2 * BNg * BSP;

    const int tid  = threadIdx.x;
    const int lane = tid & 31;
    const int w    = tid >> 5;
    const int wm   = (w & 1) * 32;   // 2 m-slots of 32 rows
    const int wn   = (w >> 1) * 16;  // 4 n-slots of 16 cols
    const int g    = lane >> 2;
    const int tg   = lane & 3;
    const int m0   = blockIdx.y * BMg;
    const int p0   = blockIdx.x * BNg;

    float alpha = 0.0f;
    if (PRELU_A) alpha = __ldg(prelu_a);

    // Per-thread tile-load coordinates (fixed): 64 rows x 8 float4 = 512, 2/thread
    int arow[2], ac4[2]; bool apred[2];
#pragma unroll
    for (int i = 0; i < 2; ++i) {
        int f4 = tid + i * 256;
        arow[i] = f4 >> 3; ac4[i] = f4 & 7;
        apred[i] = (m0 + arow[i]) < M;
    }
    int brow[2], bc4[2]; bool bpred[2];
#pragma unroll
    for (int i = 0; i < 2; ++i) {
        int f4 = tid + i * 256;
        brow[i] = f4 >> 3; bc4[i] = f4 & 7;
        bpred[i] = (p0 + brow[i]) < P;
    }

    // ldmatrix per-lane addressing
    const int a_row = lane & 15;
    const int a_kp0 = (lane >> 4) * 4;
    const int b_row = ((lane >> 4) & 1) * 8 + (lane & 7);
    const int b_kp0 = ((lane >> 3) & 1) * 4;

    float acc[2][2][4];
#pragma unroll
    for (int mt = 0; mt < 2; ++mt)
#pragma unroll
        for (int nt = 0; nt < 2; ++nt)
#pragma unroll
            for (int i = 0; i < 4; ++i) acc[mt][nt][i] = 0.0f;

    float4 pa[2], pb[2];

    // ---- prologue: load k0=0 tile into regs, store to stage 0
#pragma unroll
    for (int i = 0; i < 2; ++i)
        pa[i] = apred[i] ? __ldg((const float4*)(A + (size_t)(m0 + arow[i]) * K + ac4[i] * 4))
                         : make_float4(0.f, 0.f, 0.f, 0.f);
#pragma unroll
    for (int i = 0; i < 2; ++i)
        pb[i] = bpred[i] ? __ldg((const float4*)(B + (size_t)(p0 + brow[i]) * K + bc4[i] * 4))
                         : make_float4(0.f, 0.f, 0.f, 0.f);
    {
#pragma unroll
        for (int i = 0; i < 2; ++i) {
            float4 v = pa[i];
            if (PRELU_A) {
                v.x = v.x > 0.f ? v.x : alpha * v.x;
                v.y = v.y > 0.f ? v.y : alpha * v.y;
                v.z = v.z > 0.f ? v.z : alpha * v.z;
                v.w = v.w > 0.f ? v.w : alpha * v.w;
            }
            uint32_t h0, h1, l0, l1; cvt4(v, h0, h1, l0, l1);
            int base = arow[i] * ASP + ac4[i] * 2;
            AH[base] = h0; AH[base + 1] = h1;
            AL[base] = l0; AL[base + 1] = l1;
        }
#pragma unroll
        for (int i = 0; i < 2; ++i) {
            uint32_t h0, h1, l0, l1; cvt4(pb[i], h0, h1, l0, l1);
            int base = brow[i] * BSP + bc4[i] * 2;
            BH[base] = h0; BH[base + 1] = h1;
            BL[base] = l0; BL[base + 1] = l1;
        }
    }
    __syncthreads();

    const int niter = K / 32;
    for (int it = 0; it < niter; ++it) {
        const int cur = it & 1;
        const bool has_next = (it + 1) < niter;
        const int knext = (it + 1) * 32;

        // ---- issue next tile's LDGs early
        if (has_next) {
#pragma unroll
            for (int i = 0; i < 2; ++i)
                pa[i] = apred[i] ? __ldg((const float4*)(A + (size_t)(m0 + arow[i]) * K + knext + ac4[i] * 4))
                                 : make_float4(0.f, 0.f, 0.f, 0.f);
#pragma unroll
            for (int i = 0; i < 2; ++i)
                pb[i] = bpred[i] ? __ldg((const float4*)(B + (size_t)(p0 + brow[i]) * K + knext + bc4[i] * 4))
                                 : make_float4(0.f, 0.f, 0.f, 0.f);
        }

        // ---- MMA on current stage
        const uint32_t* cAH = AH + cur * BMg * ASP;
        const uint32_t* cAL = AL + cur * BMg * ASP;
        const uint32_t* cBH = BH + cur * BNg * BSP;
        const uint32_t* cBL = BL + cur * BNg * BSP;
#pragma unroll
        for (int ks = 0; ks < 2; ++ks) {
            uint32_t ah[2][4], al[2][4], bh[4], bl[4];
            int akp = ks * 8 + a_kp0;
            int bkp = ks * 8 + b_kp0;
#pragma unroll
            for (int mt = 0; mt < 2; ++mt) {
                int r = wm + mt * 16 + a_row;
                ldsm4(ah[mt], &cAH[r * ASP + akp]);
                ldsm4(al[mt], &cAL[r * ASP + akp]);
            }
            {
                int n = wn + b_row;
                ldsm4(bh, &cBH[n * BSP + bkp]);
                ldsm4(bl, &cBL[n * BSP + bkp]);
            }
#pragma unroll
            for (int nt = 0; nt < 2; ++nt) {
                uint32_t b0  = bh[nt * 2], b1  = bh[nt * 2 + 1];
                uint32_t lb0 = bl[nt * 2], lb1 = bl[nt * 2 + 1];
#pragma unroll
                for (int mt = 0; mt < 2; ++mt) {
                    mma16816(acc[mt][nt], ah[mt], b0, b1);
                    mma16816(acc[mt][nt], al[mt], b0, b1);
                    mma16816(acc[mt][nt], ah[mt], lb0, lb1);
                }
            }
        }

        // ---- convert + store prefetched tile into the other stage
        if (has_next) {
            uint32_t* nAH = AH + (cur ^ 1) * BMg * ASP;
            uint32_t* nAL = AL + (cur ^ 1) * BMg * ASP;
            uint32_t* nBH = BH + (cur ^ 1) * BNg * BSP;
            uint32_t* nBL = BL + (cur ^ 1) * BNg * BSP;
#pragma unroll
            for (int i = 0; i < 2; ++i) {
                float4 v = pa[i];
                if (PRELU_A) {
                    v.x = v.x > 0.f ? v.x : alpha * v.x;
                    v.y = v.y > 0.f ? v.y : alpha * v.y;
                    v.z = v.z > 0.f ? v.z : alpha * v.z;
                    v.w = v.w > 0.f ? v.w : alpha * v.w;
                }
                uint32_t h0, h1, l0, l1; cvt4(v, h0, h1, l0, l1);
                int base = arow[i] * ASP + ac4[i] * 2;
                nAH[base] = h0; nAH[base + 1] = h1;
                nAL[base] = l0; nAL[base + 1] = l1;
            }
#pragma unroll
            for (int i = 0; i < 2; ++i) {
                uint32_t h0, h1, l0, l1; cvt4(pb[i], h0, h1, l0, l1);
                int base = brow[i] * BSP + bc4[i] * 2;
                nBH[base] = h0; nBH[base + 1] = h1;
                nBL[base] = l0; nBL[base + 1] = l1;
            }
        }
        __syncthreads();
    }

    // ---- Epilogue
#pragma unroll
    for (int mt = 0; mt < 2; ++mt) {
#pragma unroll
        for (int nt = 0; nt < 2; ++nt) {
            int row0 = m0 + wm + mt * 16 + g;
            int col  = p0 + wn + nt * 8 + tg * 2;
            float b0 = 0.f, b1 = 0.f;
            if (HAS_BIAS) {
                if (col < P)     b0 = __ldg(bias + col);
                if (col + 1 < P) b1 = __ldg(bias + col + 1);
            }
            float ec0 = 0.f, ec1 = 0.f;
            if (FUSED_MS) {
                ec0 = __ldg(emb1 + 4 * D_IN + col) + __ldg(emb2 + col);
                ec1 = __ldg(emb1 + 4 * D_IN + col + 1) + __ldg(emb2 + col + 1);
            }
#pragma unroll
            for (int h = 0; h < 2; ++h) {
                int row = row0 + h * 8;
                if (row >= M) continue;
                float v0 = acc[mt][nt][h * 2 + 0] + b0;
                float v1 = acc[mt][nt][h * 2 + 1] + b1;
                if (RELU_OUT) { v0 = fmaxf(v0, 0.f); v1 = fmaxf(v1, 0.f); }
                if (FUSED_MS) {
                    bool masked = (__ldg(&g_maskbits[row >> 5]) >> (row & 31)) & 1u;
                    if (masked) { v0 = 0.f; v1 = 0.f; }
                    C[(size_t)row * P + col]      = v0;
                    C[(size_t)row * P + col + 1]  = v1;
                    C2[(size_t)row * P + col]     = v0 + ec0;
                    C2[(size_t)row * P + col + 1] = v1 + ec1;
                } else {
                    if (col < P)     C[(size_t)row * P + col]     = v0;
                    if (col + 1 < P) C[(size_t)row * P + col + 1] = v1;
                }
            }
        }
    }
}

// ---------------------------------------------------------------------------
// Build mask bitmap. Single block: zero then set.
// ---------------------------------------------------------------------------
__global__ void maskbits_kernel(const int* __restrict__ mi, int NM)
{
    const int W = (N_NODES + 31) / 32;
    for (int i = threadIdx.x; i < W; i += blockDim.x) g_maskbits[i] = 0u;
    __syncthreads();
    for (int i = threadIdx.x; i < NM; i += blockDim.x) {
        int r = __ldg(mi + i);
        if (r >= 0 && r < N_NODES)
            atomicOr(&g_maskbits[r >> 5], 1u << (r & 31));
    }
}

// ---------------------------------------------------------------------------
// Edge scatter: aggr[dst] += h[src] + emb1[et] + emb2[ed].
// One warp per FOUR edges, software-pipelined gathers, vector red.add.
// ---------------------------------------------------------------------------
__global__ void edge_kernel(const int* __restrict__ ei,
                            const int* __restrict__ ea,
                            const float* __restrict__ emb1,
                            const float* __restrict__ emb2, int E)
{
    int w = (blockIdx.x * blockDim.x + threadIdx.x) >> 5;
    int lane = threadIdx.x & 31;
    int c = lane * 4;
    int base = w * 4;
    if (base >= E) return;

    int src[4], dst[4], et[4], ed[4];
#pragma unroll
    for (int j = 0; j < 4; ++j) {
        int e = base + j;
        if (e < E) {
            src[j] = __ldg(ei + e);
            dst[j] = __ldg(ei + E + e);
            et[j]  = __ldg(ea + 2 * e);
            ed[j]  = __ldg(ea + 2 * e + 1);
        } else { src[j] = 0; dst[j] = -1; et[j] = 0; ed[j] = 0; }
    }
    float4 hv[4], e1[4], e2[4];
#pragma unroll
    for (int j = 0; j < 4; ++j) {
        hv[j] = *(const float4*)(g_h + (size_t)src[j] * D_IN + c);
        e1[j] = __ldg((const float4*)(emb1 + (size_t)et[j] * D_IN + c));
        e2[j] = __ldg((const float4*)(emb2 + (size_t)ed[j] * D_IN + c));
    }
#pragma unroll
    for (int j = 0; j < 4; ++j) {
        if (dst[j] < 0) continue;
        float m0 = hv[j].x + e1[j].x + e2[j].x;
        float m1 = hv[j].y + e1[j].y + e2[j].y;
        float m2 = hv[j].z + e1[j].z + e2[j].z;
        float m3 = hv[j].w + e1[j].w + e2[j].w;
        float* p = g_aggr + (size_t)dst[j] * D_IN + c;
        asm volatile("red.global.add.v4.f32 [%0], {%1, %2, %3, %4};"
                     :: "l"(p), "f"(m0), "f"(m1), "f"(m2), "f"(m3)
                     : "memory");
    }
}

// ---------------------------------------------------------------------------
extern "C" void kernel_launch(void* const* d_in, const int* in_sizes, int n_in,
                              void* d_out, int out_size)
{
    const float* x       = (const float*)d_in[0];
    const int*   ei      = (const int*)d_in[1];
    const int*   ea      = (const int*)d_in[2];
    const int*   mi      = (const int*)d_in[3];
    const float* prelu_a = (const float*)d_in[4];
    const float* W_enc   = (const float*)d_in[5];
    const float* emb1    = (const float*)d_in[6];
    const float* emb2    = (const float*)d_in[7];
    const float* W1      = (const float*)d_in[8];
    const float* b1      = (const float*)d_in[9];
    const float* W2      = (const float*)d_in[10];
    const float* b2      = (const float*)d_in[11];
    float*       out     = (float*)d_out;

    const int N  = in_sizes[0] / D_IN;
    const int E  = in_sizes[1] / 2;
    const int NM = in_sizes[3];

    const int SMEM_BYTES = SMEM_WORDS * 4;   // 40960

    // Idempotent, called every invocation (no static guards -- harness rule)
    cudaFuncSetAttribute(gemm_mma_kernel<true, false, false, true>,
                         cudaFuncAttributeMaxDynamicSharedMemorySize, SMEM_BYTES);
    cudaFuncSetAttribute(gemm_mma_kernel<false, true, true, false>,
                         cudaFuncAttributeMaxDynamicSharedMemorySize, SMEM_BYTES);
    cudaFuncSetAttribute(gemm_mma_kernel<false, false, true, false>,
                         cudaFuncAttributeMaxDynamicSharedMemorySize, SMEM_BYTES);

    float *h_ptr, *aggr_ptr, *hid_ptr;
    cudaGetSymbolAddress((void**)&h_ptr, g_h);
    cudaGetSymbolAddress((void**)&aggr_ptr, g_aggr);
    cudaGetSymbolAddress((void**)&hid_ptr, g_hid);

    // 0) mask bitmap
    maskbits_kernel<<<1, 1024>>>(mi, NM);

    // 1) h = mask(prelu(x) @ W_enc^T); aggr = h + emb1[4]+emb2[0]   (fused)
    {
        dim3 grid((D_IN + BNg - 1) / BNg, (N + BMg - 1) / BMg);
        gemm_mma_kernel<true, false, false, true><<<grid, 256, SMEM_BYTES>>>(
            x, W_enc, nullptr, h_ptr, aggr_ptr, N, D_IN, D_IN, prelu_a, emb1, emb2);
    }
    // 2) edge scatter-add (4 edges per warp)
    {
        int warps = (E + 3) / 4;
        long long threads = (long long)warps * 32;
        edge_kernel<<<(int)((threads + 255) / 256), 256>>>(ei, ea, emb1, emb2, E);
    }
    // 3) hid = relu(aggr @ W1^T + b1)
    {
        dim3 grid((D_FF + BNg - 1) / BNg, (N + BMg - 1) / BMg);
        gemm_mma_kernel<false, true, true, false><<<grid, 256, SMEM_BYTES>>>(
            aggr_ptr, W1, b1, hid_ptr, nullptr, N, D_IN, D_FF, nullptr, nullptr, nullptr);
    }
    // 4) out = hid @ W2^T + b2
    {
        dim3 grid((D_OUT + BNg - 1) / BNg, (N + BMg - 1) / BMg);
        gemm_mma_kernel<false, false, true, false><<<grid, 256, SMEM_BYTES>>>(
            hid_ptr, W2, b2, out, nullptr, N, D_FF, D_OUT, nullptr, nullptr, nullptr);
    }
}

// round 11
// speedup vs baseline: 1.0008x; 1.0008x over previous
#include <cuda_runtime.h>
#include <cuda_bf16.h>
#include <cstdint>

// Problem constants (fixed shapes for this problem)
#define N_NODES 50000
#define D_IN    128
#define D_FF    256
#define D_OUT   119

// Scratch (allocation-free rule: __device__ globals). 16B-aligned.
__device__ __align__(16) float g_u[(size_t)N_NODES * D_IN];      // 25.6 MB  mask(prelu(x))
__device__ __align__(16) float g_aggu[(size_t)N_NODES * D_IN];   // 25.6 MB  S·u
__device__ __align__(16) float g_hid[(size_t)N_NODES * D_FF];    // 51.2 MB
__device__ __align__(16) float g_Wf[(size_t)D_FF * D_IN];        // Wf = W1 @ W_enc  [256x128]
__device__ __align__(16) float g_E1W[3 * D_FF];                  // emb1[t] @ W1^T, t<3
__device__ __align__(16) float g_E2W[3 * D_FF];                  // emb2[d] @ W1^T, d<3
__device__ __align__(16) float g_bias2[D_FF];                    // b1 + (emb1[4]+emb2[0])@W1^T
__device__ __align__(16) int   g_cnt[(size_t)N_NODES * 8];       // per-node type counts
__device__ unsigned g_maskbits[(N_NODES + 31) / 32];

// ---------------------------------------------------------------------------
// MMA + ldmatrix primitives
// ---------------------------------------------------------------------------
__device__ __forceinline__ void mma16816(float* c, const uint32_t* a,
                                         uint32_t b0, uint32_t b1)
{
    asm volatile(
        "mma.sync.aligned.m16n8k16.row.col.f32.bf16.bf16.f32 "
        "{%0,%1,%2,%3}, {%4,%5,%6,%7}, {%8,%9}, {%0,%1,%2,%3};"
        : "+f"(c[0]), "+f"(c[1]), "+f"(c[2]), "+f"(c[3])
        : "r"(a[0]), "r"(a[1]), "r"(a[2]), "r"(a[3]), "r"(b0), "r"(b1));
}

__device__ __forceinline__ void ldsm4(uint32_t* r, const uint32_t* p)
{
    uint32_t a = (uint32_t)__cvta_generic_to_shared(p);
    asm volatile("ldmatrix.sync.aligned.m8n8.x4.shared.b16 {%0,%1,%2,%3}, [%4];"
                 : "=r"(r[0]), "=r"(r[1]), "=r"(r[2]), "=r"(r[3]) : "r"(a));
}

__device__ __forceinline__ void split_bf16(float x, __nv_bfloat16& hi, __nv_bfloat16& lo)
{
    hi = __float2bfloat16_rn(x);
    lo = __float2bfloat16_rn(x - __bfloat162float(hi));
}

__device__ __forceinline__ void cvt4(const float4& v, uint32_t& h0, uint32_t& h1,
                                     uint32_t& l0, uint32_t& l1)
{
    __nv_bfloat16 hx, lx, hy, ly, hz, lz, hw, lw;
    split_bf16(v.x, hx, lx); split_bf16(v.y, hy, ly);
    split_bf16(v.z, hz, lz); split_bf16(v.w, hw, lw);
    __nv_bfloat162 a = __nv_bfloat162(hx, hy), b = __nv_bfloat162(hz, hw);
    __nv_bfloat162 c = __nv_bfloat162(lx, ly), d = __nv_bfloat162(lz, lw);
    h0 = *(uint32_t*)&a; h1 = *(uint32_t*)&b;
    l0 = *(uint32_t*)&c; l1 = *(uint32_t*)&d;
}

// ---------------------------------------------------------------------------
// bf16-split tensor-core GEMM (R6 engine): C[M,P] = act(A @ B^T + bias [+cnt])
// acc += Ah*Bh + Al*Bh + Ah*Bl.  BM=128, BN=64, BK=32; 8 warps; warp 32x32.
// FUSED_CNT: += per-row edge-type-count * (emb @ W1^T) correction, for hid GEMM.
// ---------------------------------------------------------------------------
#define BMg 128
#define BNg 64
#define ASP 20
#define BSP 20
#define SMEM_WORDS (4 * BMg * ASP + 4 * BNg * BSP)   /* 61440 B */

template<bool RELU_OUT, bool FUSED_CNT>
__global__ __launch_bounds__(256, 2)
void gemm_mma_kernel(const float* __restrict__ A, const float* __restrict__ B,
                     const float* __restrict__ bias, float* __restrict__ C,
                     int M, int K, int P)
{
    extern __shared__ uint32_t smem[];
    uint32_t* AH = smem;
    uint32_t* AL = smem + 2 * BMg * ASP;
    uint32_t* BH = smem + 4 * BMg * ASP;
    uint32_t* BL = smem + 4 * BMg * ASP + 2 * BNg * BSP;

    const int tid  = threadIdx.x;
    const int lane = tid & 31;
    const int w    = tid >> 5;
    const int wm   = (w & 3) * 32;
    const int wn   = (w >> 2) * 32;
    const int g    = lane >> 2;
    const int tg   = lane & 3;
    const int m0   = blockIdx.y * BMg;
    const int p0   = blockIdx.x * BNg;

    int arow[4], ac4[4]; bool apred[4];
#pragma unroll
    for (int i = 0; i < 4; ++i) {
        int f4 = tid + i * 256;
        arow[i] = f4 >> 3; ac4[i] = f4 & 7;
        apred[i] = (m0 + arow[i]) < M;
    }
    int brow[2], bc4[2]; bool bpred[2];
#pragma unroll
    for (int i = 0; i < 2; ++i) {
        int f4 = tid + i * 256;
        brow[i] = f4 >> 3; bc4[i] = f4 & 7;
        bpred[i] = (p0 + brow[i]) < P;
    }

    const int a_row = lane & 15;
    const int a_kp0 = (lane >> 4) * 4;
    const int b_row = ((lane >> 4) & 1) * 8 + (lane & 7);
    const int b_kp0 = ((lane >> 3) & 1) * 4;

    float acc[2][4][4];
#pragma unroll
    for (int mt = 0; mt < 2; ++mt)
#pragma unroll
        for (int nt = 0; nt < 4; ++nt)
#pragma unroll
            for (int i = 0; i < 4; ++i) acc[mt][nt][i] = 0.0f;

    float4 pa[4], pb[2];

#pragma unroll
    for (int i = 0; i < 4; ++i)
        pa[i] = apred[i] ? __ldg((const float4*)(A + (size_t)(m0 + arow[i]) * K + ac4[i] * 4))
                         : make_float4(0.f, 0.f, 0.f, 0.f);
#pragma unroll
    for (int i = 0; i < 2; ++i)
        pb[i] = bpred[i] ? __ldg((const float4*)(B + (size_t)(p0 + brow[i]) * K + bc4[i] * 4))
                         : make_float4(0.f, 0.f, 0.f, 0.f);
    {
#pragma unroll
        for (int i = 0; i < 4; ++i) {
            uint32_t h0, h1, l0, l1; cvt4(pa[i], h0, h1, l0, l1);
            int base = arow[i] * ASP + ac4[i] * 2;
            AH[base] = h0; AH[base + 1] = h1;
            AL[base] = l0; AL[base + 1] = l1;
        }
#pragma unroll
        for (int i = 0; i < 2; ++i) {
            uint32_t h0, h1, l0, l1; cvt4(pb[i], h0, h1, l0, l1);
            int base = brow[i] * BSP + bc4[i] * 2;
            BH[base] = h0; BH[base + 1] = h1;
            BL[base] = l0; BL[base + 1] = l1;
        }
    }
    __syncthreads();

    const int niter = K / 32;
    for (int it = 0; it < niter; ++it) {
        const int cur = it & 1;
        const bool has_next = (it + 1) < niter;
        const int knext = (it + 1) * 32;

        if (has_next) {
#pragma unroll
            for (int i = 0; i < 4; ++i)
                pa[i] = apred[i] ? __ldg((const float4*)(A + (size_t)(m0 + arow[i]) * K + knext + ac4[i] * 4))
                                 : make_float4(0.f, 0.f, 0.f, 0.f);
#pragma unroll
            for (int i = 0; i < 2; ++i)
                pb[i] = bpred[i] ? __ldg((const float4*)(B + (size_t)(p0 + brow[i]) * K + knext + bc4[i] * 4))
                                 : make_float4(0.f, 0.f, 0.f, 0.f);
        }

        const uint32_t* cAH = AH + cur * BMg * ASP;
        const uint32_t* cAL = AL + cur * BMg * ASP;
        const uint32_t* cBH = BH + cur * BNg * BSP;
        const uint32_t* cBL = BL + cur * BNg * BSP;
#pragma unroll
        for (int ks = 0; ks < 2; ++ks) {
            uint32_t ah[2][4], al[2][4], bh[2][4], bl[2][4];
            int akp = ks * 8 + a_kp0;
            int bkp = ks * 8 + b_kp0;
#pragma unroll
            for (int mt = 0; mt < 2; ++mt) {
                int r = wm + mt * 16 + a_row;
                ldsm4(ah[mt], &cAH[r * ASP + akp]);
                ldsm4(al[mt], &cAL[r * ASP + akp]);
            }
#pragma unroll
            for (int p = 0; p < 2; ++p) {
                int n = wn + p * 16 + b_row;
                ldsm4(bh[p], &cBH[n * BSP + bkp]);
                ldsm4(bl[p], &cBL[n * BSP + bkp]);
            }
#pragma unroll
            for (int p = 0; p < 2; ++p) {
#pragma unroll
                for (int half = 0; half < 2; ++half) {
                    int nt = p * 2 + half;
                    uint32_t b0  = bh[p][half * 2], b1  = bh[p][half * 2 + 1];
                    uint32_t lb0 = bl[p][half * 2], lb1 = bl[p][half * 2 + 1];
#pragma unroll
                    for (int mt = 0; mt < 2; ++mt) {
                        mma16816(acc[mt][nt], ah[mt], b0, b1);
                        mma16816(acc[mt][nt], al[mt], b0, b1);
                        mma16816(acc[mt][nt], ah[mt], lb0, lb1);
                    }
                }
            }
        }

        if (has_next) {
            uint32_t* nAH = AH + (cur ^ 1) * BMg * ASP;
            uint32_t* nAL = AL + (cur ^ 1) * BMg * ASP;
            uint32_t* nBH = BH + (cur ^ 1) * BNg * BSP;
            uint32_t* nBL = BL + (cur ^ 1) * BNg * BSP;
#pragma unroll
            for (int i = 0; i < 4; ++i) {
                uint32_t h0, h1, l0, l1; cvt4(pa[i], h0, h1, l0, l1);
                int base = arow[i] * ASP + ac4[i] * 2;
                nAH[base] = h0; nAH[base + 1] = h1;
                nAL[base] = l0; nAL[base + 1] = l1;
            }
#pragma unroll
            for (int i = 0; i < 2; ++i) {
                uint32_t h0, h1, l0, l1; cvt4(pb[i], h0, h1, l0, l1);
                int base = brow[i] * BSP + bc4[i] * 2;
                nBH[base] = h0; nBH[base + 1] = h1;
                nBL[base] = l0; nBL[base + 1] = l1;
            }
        }
        __syncthreads();
    }

    // ---- Epilogue
#pragma unroll
    for (int mt = 0; mt < 2; ++mt) {
#pragma unroll
        for (int nt = 0; nt < 4; ++nt) {
            int row0 = m0 + wm + mt * 16 + g;
            int col  = p0 + wn + nt * 8 + tg * 2;
            float b0 = 0.f, b1 = 0.f;
            if (col < P)     b0 = __ldg(bias + col);
            if (col + 1 < P) b1 = __ldg(bias + col + 1);
            float e1a[3], e1b[3], e2a[3], e2b[3];
            if (FUSED_CNT) {
#pragma unroll
                for (int t = 0; t < 3; ++t) {
                    e1a[t] = __ldg(g_E1W + t * D_FF + col);
                    e1b[t] = __ldg(g_E1W + t * D_FF + col + 1);
                    e2a[t] = __ldg(g_E2W + t * D_FF + col);
                    e2b[t] = __ldg(g_E2W + t * D_FF + col + 1);
                }
            }
#pragma unroll
            for (int h = 0; h < 2; ++h) {
                int row = row0 + h * 8;
                if (row >= M) continue;
                float v0 = acc[mt][nt][h * 2 + 0] + b0;
                float v1 = acc[mt][nt][h * 2 + 1] + b1;
                if (FUSED_CNT) {
                    int4 ca = __ldg((const int4*)(g_cnt + (size_t)row * 8));
                    int4 cb = __ldg((const int4*)(g_cnt + (size_t)row * 8 + 4));
                    float c10 = (float)ca.x, c11 = (float)ca.y, c12 = (float)ca.z;
                    float c20 = (float)cb.x, c21 = (float)cb.y, c22 = (float)cb.z;
                    v0 += c10 * e1a[0] + c11 * e1a[1] + c12 * e1a[2]
                        + c20 * e2a[0] + c21 * e2a[1] + c22 * e2a[2];
                    v1 += c10 * e1b[0] + c11 * e1b[1] + c12 * e1b[2]
                        + c20 * e2b[0] + c21 * e2b[1] + c22 * e2b[2];
                }
                if (RELU_OUT) { v0 = fmaxf(v0, 0.f); v1 = fmaxf(v1, 0.f); }
                if (col < P)     C[(size_t)row * P + col]     = v0;
                if (col + 1 < P) C[(size_t)row * P + col + 1] = v1;
            }
        }
    }
}

// ---------------------------------------------------------------------------
// Mask bitmap. Single block: zero then set.
// ---------------------------------------------------------------------------
__global__ void maskbits_kernel(const int* __restrict__ mi, int NM)
{
    const int W = (N_NODES + 31) / 32;
    for (int i = threadIdx.x; i < W; i += blockDim.x) g_maskbits[i] = 0u;
    __syncthreads();
    for (int i = threadIdx.x; i < NM; i += blockDim.x) {
        int r = __ldg(mi + i);
        if (r >= 0 && r < N_NODES)
            atomicOr(&g_maskbits[r >> 5], 1u << (r & 31));
    }
}

// ---------------------------------------------------------------------------
// Zero per-node counts.
// ---------------------------------------------------------------------------
__global__ void zero_cnt_kernel()
{
    int t = blockIdx.x * blockDim.x + threadIdx.x;
    if (t < N_NODES * 2)
        *(int4*)(g_cnt + (size_t)t * 4) = make_int4(0, 0, 0, 0);
}

// ---------------------------------------------------------------------------
// Per-node edge-type counts. One thread per edge.
// ---------------------------------------------------------------------------
__global__ void count_kernel(const int* __restrict__ ei, const int* __restrict__ ea, int E)
{
    int e = blockIdx.x * blockDim.x + threadIdx.x;
    if (e >= E) return;
    int dst = __ldg(ei + E + e);
    int et  = __ldg(ea + 2 * e);
    int ed  = __ldg(ea + 2 * e + 1);
    atomicAdd(&g_cnt[(size_t)dst * 8 + et], 1);
    atomicAdd(&g_cnt[(size_t)dst * 8 + 4 + ed], 1);
}

// ---------------------------------------------------------------------------
// Precompute: Wf = W1 @ W_enc [256x128]; E1W/E2W = emb @ W1^T [3x256 each];
// bias2 = b1 + (emb1[4]+emb2[0]) @ W1^T. One block per output row j (256).
// ---------------------------------------------------------------------------
__global__ void prep_kernel(const float* __restrict__ W_enc,
                            const float* __restrict__ emb1,
                            const float* __restrict__ emb2,
                            const float* __restrict__ W1,
                            const float* __restrict__ b1)
{
    __shared__ float w1row[D_IN];
    int j = blockIdx.x;       // 0..255
    int k = threadIdx.x;      // 0..127
    w1row[k] = __ldg(W1 + (size_t)j * D_IN + k);
    __syncthreads();

    float s = 0.f;
#pragma unroll 8
    for (int i = 0; i < D_IN; ++i)
        s += w1row[i] * __ldg(W_enc + (size_t)i * D_IN + k);
    g_Wf[(size_t)j * D_IN + k] = s;

    if (k < 3) {
        float s1 = 0.f;
        for (int i = 0; i < D_IN; ++i)
            s1 += __ldg(emb1 + (size_t)k * D_IN + i) * w1row[i];
        g_E1W[k * D_FF + j] = s1;
    } else if (k < 6) {
        int d = k - 3;
        float s2 = 0.f;
        for (int i = 0; i < D_IN; ++i)
            s2 += __ldg(emb2 + (size_t)d * D_IN + i) * w1row[i];
        g_E2W[d * D_FF + j] = s2;
    } else if (k == 6) {
        float s3 = 0.f;
        for (int i = 0; i < D_IN; ++i)
            s3 += (__ldg(emb1 + 4 * D_IN + i) + __ldg(emb2 + i)) * w1row[i];
        g_bias2[j] = __ldg(b1 + j) + s3;
    }
}

// ---------------------------------------------------------------------------
// u = mask(prelu(x)); agg_u = u (self-loop init). One thread per float4.
// ---------------------------------------------------------------------------
__global__ void u_kernel(const float* __restrict__ x, const float* __restrict__ prelu_a, int N)
{
    int t = blockIdx.x * blockDim.x + threadIdx.x;
    if (t >= N * (D_IN / 4)) return;
    int i = t >> 5;
    int c = (t & 31) * 4;
    float alpha = __ldg(prelu_a);
    float4 v = __ldg((const float4*)(x + (size_t)i * D_IN + c));
    v.x = v.x > 0.f ? v.x : alpha * v.x;
    v.y = v.y > 0.f ? v.y : alpha * v.y;
    v.z = v.z > 0.f ? v.z : alpha * v.z;
    v.w = v.w > 0.f ? v.w : alpha * v.w;
    bool masked = (__ldg(&g_maskbits[i >> 5]) >> (i & 31)) & 1u;
    if (masked) v = make_float4(0.f, 0.f, 0.f, 0.f);
    *(float4*)(g_u + (size_t)i * D_IN + c)    = v;
    *(float4*)(g_aggu + (size_t)i * D_IN + c) = v;
}

// ---------------------------------------------------------------------------
// Edge scatter: agg_u[dst] += u[src]. One warp per FOUR edges, pipelined.
// ---------------------------------------------------------------------------
__global__ void edge_kernel(const int* __restrict__ ei, int E)
{
    int w = (blockIdx.x * blockDim.x + threadIdx.x) >> 5;
    int lane = threadIdx.x & 31;
    int c = lane * 4;
    int base = w * 4;
    if (base >= E) return;

    int src[4], dst[4];
#pragma unroll
    for (int j = 0; j < 4; ++j) {
        int e = base + j;
        if (e < E) {
            src[j] = __ldg(ei + e);
            dst[j] = __ldg(ei + E + e);
        } else { src[j] = 0; dst[j] = -1; }
    }
    float4 hv[4];
#pragma unroll
    for (int j = 0; j < 4; ++j)
        hv[j] = *(const float4*)(g_u + (size_t)src[j] * D_IN + c);
#pragma unroll
    for (int j = 0; j < 4; ++j) {
        if (dst[j] < 0) continue;
        float* p = g_aggu + (size_t)dst[j] * D_IN + c;
        asm volatile("red.global.add.v4.f32 [%0], {%1, %2, %3, %4};"
                     :: "l"(p), "f"(hv[j].x), "f"(hv[j].y), "f"(hv[j].z), "f"(hv[j].w)
                     : "memory");
    }
}

// ---------------------------------------------------------------------------
extern "C" void kernel_launch(void* const* d_in, const int* in_sizes, int n_in,
                              void* d_out, int out_size)
{
    const float* x       = (const float*)d_in[0];
    const int*   ei      = (const int*)d_in[1];
    const int*   ea      = (const int*)d_in[2];
    const int*   mi      = (const int*)d_in[3];
    const float* prelu_a = (const float*)d_in[4];
    const float* W_enc   = (const float*)d_in[5];
    const float* emb1    = (const float*)d_in[6];
    const float* emb2    = (const float*)d_in[7];
    const float* W1      = (const float*)d_in[8];
    const float* b1      = (const float*)d_in[9];
    const float* W2      = (const float*)d_in[10];
    const float* b2      = (const float*)d_in[11];
    float*       out     = (float*)d_out;

    const int N  = in_sizes[0] / D_IN;
    const int E  = in_sizes[1] / 2;
    const int NM = in_sizes[3];

    const int SMEM_BYTES = SMEM_WORDS * 4;   // 61440

    // Idempotent, called every invocation (no static guards -- harness rule)
    cudaFuncSetAttribute(gemm_mma_kernel<true, true>,
                         cudaFuncAttributeMaxDynamicSharedMemorySize, SMEM_BYTES);
    cudaFuncSetAttribute(gemm_mma_kernel<false, false>,
                         cudaFuncAttributeMaxDynamicSharedMemorySize, SMEM_BYTES);

    float *u_ptr, *aggu_ptr, *hid_ptr, *wf_ptr, *bias2_ptr;
    cudaGetSymbolAddress((void**)&u_ptr, g_u);
    cudaGetSymbolAddress((void**)&aggu_ptr, g_aggu);
    cudaGetSymbolAddress((void**)&hid_ptr, g_hid);
    cudaGetSymbolAddress((void**)&wf_ptr, g_Wf);
    cudaGetSymbolAddress((void**)&bias2_ptr, g_bias2);

    // 0) mask bitmap; zero counts; precompute folded weights
    maskbits_kernel<<<1, 1024>>>(mi, NM);
    zero_cnt_kernel<<<(N_NODES * 2 + 255) / 256, 256>>>();
    prep_kernel<<<D_FF, D_IN>>>(W_enc, emb1, emb2, W1, b1);

    // 1) u = mask(prelu(x)); agg_u = u
    {
        int threads = N * (D_IN / 4);
        u_kernel<<<(threads + 255) / 256, 256>>>(x, prelu_a, N);
    }
    // 2) per-node edge-type counts
    count_kernel<<<(E + 255) / 256, 256>>>(ei, ea, E);

    // 3) edge scatter: agg_u[dst] += u[src]
    {
        int warps = (E + 3) / 4;
        long long threads = (long long)warps * 32;
        edge_kernel<<<(int)((threads + 255) / 256), 256>>>(ei, E);
    }
    // 4) hid = relu(agg_u @ Wf^T + bias2 + cnt-correction)
    {
        dim3 grid((D_FF + BNg - 1) / BNg, (N + BMg - 1) / BMg);
        gemm_mma_kernel<true, true><<<grid, 256, SMEM_BYTES>>>(
            aggu_ptr, wf_ptr, bias2_ptr, hid_ptr, N, D_IN, D_FF);
    }
    // 5) out = hid @ W2^T + b2
    {
        dim3 grid((D_OUT + BNg - 1) / BNg, (N + BMg - 1) / BMg);
        gemm_mma_kernel<false, false><<<grid, 256, SMEM_BYTES>>>(
            hid_ptr, W2, b2, out, N, D_FF, D_OUT);
    }
}

// round 14
// speedup vs baseline: 1.0439x; 1.0430x over previous
#include <cuda_runtime.h>
#include <cuda_bf16.h>
#include <cstdint>

// Problem constants (fixed shapes for this problem)
#define N_NODES 50000
#define D_IN    128
#define D_FF    256
#define D_OUT   119

// Scratch (allocation-free rule: __device__ globals). 16B-aligned.
__device__ __align__(16) float g_u[(size_t)N_NODES * D_IN];      // mask(prelu(x))
__device__ __align__(16) float g_aggu[(size_t)N_NODES * D_IN];   // S·u
__device__ __align__(16) float g_hid[(size_t)N_NODES * D_FF];
__device__ __align__(16) float g_Wf[(size_t)D_FF * D_IN];        // W1 @ W_enc
__device__ __align__(16) float g_E1W[3 * D_FF];                  // emb1[t] @ W1^T
__device__ __align__(16) float g_E2W[3 * D_FF];                  // emb2[d] @ W1^T
__device__ __align__(16) float g_bias2[D_FF];                    // b1 + (emb1[4]+emb2[0])@W1^T
__device__ __align__(16) int   g_cnt[(size_t)N_NODES * 8];       // per-node type counts
__device__ unsigned g_maskbits[(N_NODES + 31) / 32];

// ---------------------------------------------------------------------------
// MMA + ldmatrix primitives
// ---------------------------------------------------------------------------
__device__ __forceinline__ void mma16816(float* c, const uint32_t* a,
                                         uint32_t b0, uint32_t b1)
{
    asm volatile(
        "mma.sync.aligned.m16n8k16.row.col.f32.bf16.bf16.f32 "
        "{%0,%1,%2,%3}, {%4,%5,%6,%7}, {%8,%9}, {%0,%1,%2,%3};"
        : "+f"(c[0]), "+f"(c[1]), "+f"(c[2]), "+f"(c[3])
        : "r"(a[0]), "r"(a[1]), "r"(a[2]), "r"(a[3]), "r"(b0), "r"(b1));
}

__device__ __forceinline__ void ldsm4(uint32_t* r, const uint32_t* p)
{
    uint32_t a = (uint32_t)__cvta_generic_to_shared(p);
    asm volatile("ldmatrix.sync.aligned.m8n8.x4.shared.b16 {%0,%1,%2,%3}, [%4];"
                 : "=r"(r[0]), "=r"(r[1]), "=r"(r[2]), "=r"(r[3]) : "r"(a));
}

__device__ __forceinline__ void split_bf16(float x, __nv_bfloat16& hi, __nv_bfloat16& lo)
{
    hi = __float2bfloat16_rn(x);
    lo = __float2bfloat16_rn(x - __bfloat162float(hi));
}

__device__ __forceinline__ void cvt4(const float4& v, uint32_t& h0, uint32_t& h1,
                                     uint32_t& l0, uint32_t& l1)
{
    __nv_bfloat16 hx, lx, hy, ly, hz, lz, hw, lw;
    split_bf16(v.x, hx, lx); split_bf16(v.y, hy, ly);
    split_bf16(v.z, hz, lz); split_bf16(v.w, hw, lw);
    __nv_bfloat162 a = __nv_bfloat162(hx, hy), b = __nv_bfloat162(hz, hw);
    __nv_bfloat162 c = __nv_bfloat162(lx, ly), d = __nv_bfloat162(lz, lw);
    h0 = *(uint32_t*)&a; h1 = *(uint32_t*)&b;
    l0 = *(uint32_t*)&c; l1 = *(uint32_t*)&d;
}

// ---------------------------------------------------------------------------
// bf16-split tensor-core GEMM (R6 engine): C[M,P] = act(A @ B^T + bias [+cnt])
// BM=128, BN=64, BK=32; 8 warps; warp 32x32; 2-stage pipeline.
// FUSED_CNT: adds rank-6 correction cnt[row] · (emb@W1^T)[col]; e-values live
// in a DEDICATED smem region (no aliasing of the pipeline buffers).
// ---------------------------------------------------------------------------
#define BMg 128
#define BNg 64
#define ASP 20
#define BSP 20
#define PIPE_WORDS (4 * BMg * ASP + 4 * BNg * BSP)        /* 15360 words */
#define SMEM_WORDS (PIPE_WORDS + 6 * BNg)                 /* + 384 words for sE */

template<bool RELU_OUT, bool FUSED_CNT>
__global__ __launch_bounds__(256, 2)
void gemm_mma_kernel(const float* __restrict__ A, const float* __restrict__ B,
                     const float* __restrict__ bias, float* __restrict__ C,
                     int M, int K, int P)
{
    extern __shared__ uint32_t smem[];
    uint32_t* AH = smem;
    uint32_t* AL = smem + 2 * BMg * ASP;
    uint32_t* BH = smem + 4 * BMg * ASP;
    uint32_t* BL = smem + 4 * BMg * ASP + 2 * BNg * BSP;
    float*    sE = (float*)(smem + PIPE_WORDS);     // dedicated [6][BNg]

    const int tid  = threadIdx.x;
    const int lane = tid & 31;
    const int w    = tid >> 5;
    const int wm   = (w & 3) * 32;
    const int wn   = (w >> 2) * 32;
    const int g    = lane >> 2;
    const int tg   = lane & 3;
    const int m0   = blockIdx.y * BMg;
    const int p0   = blockIdx.x * BNg;

    // FUSED_CNT: load e-values into dedicated smem up front (no aliasing).
    if (FUSED_CNT) {
        for (int t = tid; t < 6 * BNg; t += 256) {
            int r = t / BNg, c = t - r * BNg;
            sE[t] = (r < 3) ? __ldg(g_E1W + r * D_FF + p0 + c)
                            : __ldg(g_E2W + (r - 3) * D_FF + p0 + c);
        }
    }

    int arow[4], ac4[4]; bool apred[4];
#pragma unroll
    for (int i = 0; i < 4; ++i) {
        int f4 = tid + i * 256;
        arow[i] = f4 >> 3; ac4[i] = f4 & 7;
        apred[i] = (m0 + arow[i]) < M;
    }
    int brow[2], bc4[2]; bool bpred[2];
#pragma unroll
    for (int i = 0; i < 2; ++i) {
        int f4 = tid + i * 256;
        brow[i] = f4 >> 3; bc4[i] = f4 & 7;
        bpred[i] = (p0 + brow[i]) < P;
    }

    const int a_row = lane & 15;
    const int a_kp0 = (lane >> 4) * 4;
    const int b_row = ((lane >> 4) & 1) * 8 + (lane & 7);
    const int b_kp0 = ((lane >> 3) & 1) * 4;

    float acc[2][4][4];
#pragma unroll
    for (int mt = 0; mt < 2; ++mt)
#pragma unroll
        for (int nt = 0; nt < 4; ++nt)
#pragma unroll
            for (int i = 0; i < 4; ++i) acc[mt][nt][i] = 0.0f;

    float4 pa[4], pb[2];

#pragma unroll
    for (int i = 0; i < 4; ++i)
        pa[i] = apred[i] ? __ldg((const float4*)(A + (size_t)(m0 + arow[i]) * K + ac4[i] * 4))
                         : make_float4(0.f, 0.f, 0.f, 0.f);
#pragma unroll
    for (int i = 0; i < 2; ++i)
        pb[i] = bpred[i] ? __ldg((const float4*)(B + (size_t)(p0 + brow[i]) * K + bc4[i] * 4))
                         : make_float4(0.f, 0.f, 0.f, 0.f);
    {
#pragma unroll
        for (int i = 0; i < 4; ++i) {
            uint32_t h0, h1, l0, l1; cvt4(pa[i], h0, h1, l0, l1);
            int base = arow[i] * ASP + ac4[i] * 2;
            AH[base] = h0; AH[base + 1] = h1;
            AL[base] = l0; AL[base + 1] = l1;
        }
#pragma unroll
        for (int i = 0; i < 2; ++i) {
            uint32_t h0, h1, l0, l1; cvt4(pb[i], h0, h1, l0, l1);
            int base = brow[i] * BSP + bc4[i] * 2;
            BH[base] = h0; BH[base + 1] = h1;
            BL[base] = l0; BL[base + 1] = l1;
        }
    }
    __syncthreads();

    const int niter = K / 32;
    for (int it = 0; it < niter; ++it) {
        const int cur = it & 1;
        const bool has_next = (it + 1) < niter;
        const int knext = (it + 1) * 32;

        if (has_next) {
#pragma unroll
            for (int i = 0; i < 4; ++i)
                pa[i] = apred[i] ? __ldg((const float4*)(A + (size_t)(m0 + arow[i]) * K + knext + ac4[i] * 4))
                                 : make_float4(0.f, 0.f, 0.f, 0.f);
#pragma unroll
            for (int i = 0; i < 2; ++i)
                pb[i] = bpred[i] ? __ldg((const float4*)(B + (size_t)(p0 + brow[i]) * K + knext + bc4[i] * 4))
                                 : make_float4(0.f, 0.f, 0.f, 0.f);
        }

        const uint32_t* cAH = AH + cur * BMg * ASP;
        const uint32_t* cAL = AL + cur * BMg * ASP;
        const uint32_t* cBH = BH + cur * BNg * BSP;
        const uint32_t* cBL = BL + cur * BNg * BSP;
#pragma unroll
        for (int ks = 0; ks < 2; ++ks) {
            uint32_t ah[2][4], al[2][4], bh[2][4], bl[2][4];
            int akp = ks * 8 + a_kp0;
            int bkp = ks * 8 + b_kp0;
#pragma unroll
            for (int mt = 0; mt < 2; ++mt) {
                int r = wm + mt * 16 + a_row;
                ldsm4(ah[mt], &cAH[r * ASP + akp]);
                ldsm4(al[mt], &cAL[r * ASP + akp]);
            }
#pragma unroll
            for (int p = 0; p < 2; ++p) {
                int n = wn + p * 16 + b_row;
                ldsm4(bh[p], &cBH[n * BSP + bkp]);
                ldsm4(bl[p], &cBL[n * BSP + bkp]);
            }
#pragma unroll
            for (int p = 0; p < 2; ++p) {
#pragma unroll
                for (int half = 0; half < 2; ++half) {
                    int nt = p * 2 + half;
                    uint32_t b0  = bh[p][half * 2], b1  = bh[p][half * 2 + 1];
                    uint32_t lb0 = bl[p][half * 2], lb1 = bl[p][half * 2 + 1];
#pragma unroll
                    for (int mt = 0; mt < 2; ++mt) {
                        mma16816(acc[mt][nt], ah[mt], b0, b1);
                        mma16816(acc[mt][nt], al[mt], b0, b1);
                        mma16816(acc[mt][nt], ah[mt], lb0, lb1);
                    }
                }
            }
        }

        if (has_next) {
            uint32_t* nAH = AH + (cur ^ 1) * BMg * ASP;
            uint32_t* nAL = AL + (cur ^ 1) * BMg * ASP;
            uint32_t* nBH = BH + (cur ^ 1) * BNg * BSP;
            uint32_t* nBL = BL + (cur ^ 1) * BNg * BSP;
#pragma unroll
            for (int i = 0; i < 4; ++i) {
                uint32_t h0, h1, l0, l1; cvt4(pa[i], h0, h1, l0, l1);
                int base = arow[i] * ASP + ac4[i] * 2;
                nAH[base] = h0; nAH[base + 1] = h1;
                nAL[base] = l0; nAL[base + 1] = l1;
            }
#pragma unroll
            for (int i = 0; i < 2; ++i) {
                uint32_t h0, h1, l0, l1; cvt4(pb[i], h0, h1, l0, l1);
                int base = brow[i] * BSP + bc4[i] * 2;
                nBH[base] = h0; nBH[base + 1] = h1;
                nBL[base] = l0; nBL[base + 1] = l1;
            }
        }
        __syncthreads();
    }

    // ---- Epilogue ----
    float crow[2][2][6];
    if (FUSED_CNT) {
#pragma unroll
        for (int mt = 0; mt < 2; ++mt)
#pragma unroll
            for (int hh = 0; hh < 2; ++hh) {
                int row = m0 + wm + mt * 16 + g + hh * 8;
                if (row < M) {
                    int4 ca = __ldg((const int4*)(g_cnt + (size_t)row * 8));
                    int4 cb = __ldg((const int4*)(g_cnt + (size_t)row * 8 + 4));
                    crow[mt][hh][0] = (float)ca.x;
                    crow[mt][hh][1] = (float)ca.y;
                    crow[mt][hh][2] = (float)ca.z;
                    crow[mt][hh][3] = (float)cb.x;
                    crow[mt][hh][4] = (float)cb.y;
                    crow[mt][hh][5] = (float)cb.z;
                } else {
#pragma unroll
                    for (int t = 0; t < 6; ++t) crow[mt][hh][t] = 0.f;
                }
            }
    }

#pragma unroll
    for (int nt = 0; nt < 4; ++nt) {
        int cloc = wn + nt * 8 + tg * 2;
        int col  = p0 + cloc;
        float b0 = 0.f, b1 = 0.f;
        if (col < P)     b0 = __ldg(bias + col);
        if (col + 1 < P) b1 = __ldg(bias + col + 1);
        float ea0[6], ea1[6];
        if (FUSED_CNT) {
#pragma unroll
            for (int t = 0; t < 6; ++t) {
                ea0[t] = sE[t * BNg + cloc];
                ea1[t] = sE[t * BNg + cloc + 1];
            }
        }
#pragma unroll
        for (int mt = 0; mt < 2; ++mt) {
#pragma unroll
            for (int hh = 0; hh < 2; ++hh) {
                int row = m0 + wm + mt * 16 + g + hh * 8;
                if (row >= M) continue;
                float v0 = acc[mt][nt][hh * 2 + 0] + b0;
                float v1 = acc[mt][nt][hh * 2 + 1] + b1;
                if (FUSED_CNT) {
#pragma unroll
                    for (int t = 0; t < 6; ++t) {
                        v0 += crow[mt][hh][t] * ea0[t];
                        v1 += crow[mt][hh][t] * ea1[t];
                    }
                }
                if (RELU_OUT) { v0 = fmaxf(v0, 0.f); v1 = fmaxf(v1, 0.f); }
                if (col < P)     C[(size_t)row * P + col]     = v0;
                if (col + 1 < P) C[(size_t)row * P + col + 1] = v1;
            }
        }
    }
}

// ---------------------------------------------------------------------------
// Mask bitmap. Single block: zero then set.
// ---------------------------------------------------------------------------
__global__ void maskbits_kernel(const int* __restrict__ mi, int NM)
{
    const int W = (N_NODES + 31) / 32;
    for (int i = threadIdx.x; i < W; i += blockDim.x) g_maskbits[i] = 0u;
    __syncthreads();
    for (int i = threadIdx.x; i < NM; i += blockDim.x) {
        int r = __ldg(mi + i);
        if (r >= 0 && r < N_NODES)
            atomicOr(&g_maskbits[r >> 5], 1u << (r & 31));
    }
}

// ---------------------------------------------------------------------------
// Precompute: Wf = W1 @ W_enc; E1W/E2W = emb @ W1^T; bias2.
// One block per output row j (256 blocks x 128 threads).
// ---------------------------------------------------------------------------
__global__ void prep_kernel(const float* __restrict__ W_enc,
                            const float* __restrict__ emb1,
                            const float* __restrict__ emb2,
                            const float* __restrict__ W1,
                            const float* __restrict__ b1)
{
    __shared__ float w1row[D_IN];
    int j = blockIdx.x;
    int k = threadIdx.x;
    w1row[k] = __ldg(W1 + (size_t)j * D_IN + k);
    __syncthreads();

    float s = 0.f;
#pragma unroll 8
    for (int i = 0; i < D_IN; ++i)
        s += w1row[i] * __ldg(W_enc + (size_t)i * D_IN + k);
    g_Wf[(size_t)j * D_IN + k] = s;

    if (k < 3) {
        float s1 = 0.f;
#pragma unroll 8
        for (int i = 0; i < D_IN; ++i)
            s1 += __ldg(emb1 + (size_t)k * D_IN + i) * w1row[i];
        g_E1W[k * D_FF + j] = s1;
    } else if (k < 6) {
        int d = k - 3;
        float s2 = 0.f;
#pragma unroll 8
        for (int i = 0; i < D_IN; ++i)
            s2 += __ldg(emb2 + (size_t)d * D_IN + i) * w1row[i];
        g_E2W[d * D_FF + j] = s2;
    } else if (k == 6) {
        float s3 = 0.f;
#pragma unroll 8
        for (int i = 0; i < D_IN; ++i)
            s3 += (__ldg(emb1 + 4 * D_IN + i) + __ldg(emb2 + i)) * w1row[i];
        g_bias2[j] = __ldg(b1 + j) + s3;
    }
}

// ---------------------------------------------------------------------------
// u = mask(prelu(x)); agg_u = u; also zero cnt (first 100k threads).
// ---------------------------------------------------------------------------
__global__ void u_kernel(const float* __restrict__ x, const float* __restrict__ prelu_a, int N)
{
    int t = blockIdx.x * blockDim.x + threadIdx.x;
    if (t < N_NODES * 2)
        *(int4*)(g_cnt + (size_t)t * 4) = make_int4(0, 0, 0, 0);
    if (t >= N * (D_IN / 4)) return;
    int i = t >> 5;
    int c = (t & 31) * 4;
    float alpha = __ldg(prelu_a);
    float4 v = __ldg((const float4*)(x + (size_t)i * D_IN + c));
    v.x = v.x > 0.f ? v.x : alpha * v.x;
    v.y = v.y > 0.f ? v.y : alpha * v.y;
    v.z = v.z > 0.f ? v.z : alpha * v.z;
    v.w = v.w > 0.f ? v.w : alpha * v.w;
    bool masked = (__ldg(&g_maskbits[i >> 5]) >> (i & 31)) & 1u;
    if (masked) v = make_float4(0.f, 0.f, 0.f, 0.f);
    *(float4*)(g_u + (size_t)i * D_IN + c)    = v;
    *(float4*)(g_aggu + (size_t)i * D_IN + c) = v;
}

// ---------------------------------------------------------------------------
// Edge scatter: agg_u[dst] += u[src]; lanes 0-3 also bump edge-type counts
// (dst re-loaded directly -- no dynamic local-array indexing).
// One warp per FOUR edges, software-pipelined gathers, vector red.add.
// ---------------------------------------------------------------------------
__global__ void edge_kernel(const int* __restrict__ ei, const int* __restrict__ ea, int E)
{
    int w = (blockIdx.x * blockDim.x + threadIdx.x) >> 5;
    int lane = threadIdx.x & 31;
    int c = lane * 4;
    int base = w * 4;
    if (base >= E) return;

    int src[4], dst[4];
#pragma unroll
    for (int j = 0; j < 4; ++j) {
        int e = base + j;
        if (e < E) {
            src[j] = __ldg(ei + e);
            dst[j] = __ldg(ei + E + e);
        } else { src[j] = 0; dst[j] = -1; }
    }
    // counts: lanes 0-3 handle edge base+lane (direct reload, no dyn indexing)
    if (lane < 4) {
        int e = base + lane;
        if (e < E) {
            int d  = __ldg(ei + E + e);
            int t1 = __ldg(ea + 2 * e);
            int t2 = __ldg(ea + 2 * e + 1);
            atomicAdd(&g_cnt[(size_t)d * 8 + t1], 1);
            atomicAdd(&g_cnt[(size_t)d * 8 + 4 + t2], 1);
        }
    }
    float4 hv[4];
#pragma unroll
    for (int j = 0; j < 4; ++j)
        hv[j] = *(const float4*)(g_u + (size_t)src[j] * D_IN + c);
#pragma unroll
    for (int j = 0; j < 4; ++j) {
        if (dst[j] < 0) continue;
        float* p = g_aggu + (size_t)dst[j] * D_IN + c;
        asm volatile("red.global.add.v4.f32 [%0], {%1, %2, %3, %4};"
                     :: "l"(p), "f"(hv[j].x), "f"(hv[j].y), "f"(hv[j].z), "f"(hv[j].w)
                     : "memory");
    }
}

// ---------------------------------------------------------------------------
extern "C" void kernel_launch(void* const* d_in, const int* in_sizes, int n_in,
                              void* d_out, int out_size)
{
    const float* x       = (const float*)d_in[0];
    const int*   ei      = (const int*)d_in[1];
    const int*   ea      = (const int*)d_in[2];
    const int*   mi      = (const int*)d_in[3];
    const float* prelu_a = (const float*)d_in[4];
    const float* W_enc   = (const float*)d_in[5];
    const float* emb1    = (const float*)d_in[6];
    const float* emb2    = (const float*)d_in[7];
    const float* W1      = (const float*)d_in[8];
    const float* b1      = (const float*)d_in[9];
    const float* W2      = (const float*)d_in[10];
    const float* b2      = (const float*)d_in[11];
    float*       out     = (float*)d_out;

    const int N  = in_sizes[0] / D_IN;
    const int E  = in_sizes[1] / 2;
    const int NM = in_sizes[3];

    const int SMEM_BYTES = SMEM_WORDS * 4;   // 62976

    // Idempotent, called every invocation (no static guards -- harness rule)
    cudaFuncSetAttribute(gemm_mma_kernel<true, true>,
                         cudaFuncAttributeMaxDynamicSharedMemorySize, SMEM_BYTES);
    cudaFuncSetAttribute(gemm_mma_kernel<false, false>,
                         cudaFuncAttributeMaxDynamicSharedMemorySize, SMEM_BYTES);

    float *aggu_ptr, *hid_ptr, *wf_ptr, *bias2_ptr;
    cudaGetSymbolAddress((void**)&aggu_ptr, g_aggu);
    cudaGetSymbolAddress((void**)&hid_ptr, g_hid);
    cudaGetSymbolAddress((void**)&wf_ptr, g_Wf);
    cudaGetSymbolAddress((void**)&bias2_ptr, g_bias2);

    // 0) mask bitmap; folded-weight precompute
    maskbits_kernel<<<1, 1024>>>(mi, NM);
    prep_kernel<<<D_FF, D_IN>>>(W_enc, emb1, emb2, W1, b1);

    // 1) u = mask(prelu(x)); agg_u = u; zero counts
    {
        int threads = N * (D_IN / 4);
        u_kernel<<<(threads + 255) / 256, 256>>>(x, prelu_a, N);
    }
    // 2) edge scatter + counts
    {
        int warps = (E + 3) / 4;
        long long threads = (long long)warps * 32;
        edge_kernel<<<(int)((threads + 255) / 256), 256>>>(ei, ea, E);
    }
    // 3) hid = relu(agg_u @ Wf^T + bias2 + cnt-correction)
    {
        dim3 grid((D_FF + BNg - 1) / BNg, (N + BMg - 1) / BMg);
        gemm_mma_kernel<true, true><<<grid, 256, SMEM_BYTES>>>(
            aggu_ptr, wf_ptr, bias2_ptr, hid_ptr, N, D_IN, D_FF);
    }
    // 4) out = hid @ W2^T + b2
    {
        dim3 grid((D_OUT + BNg - 1) / BNg, (N + BMg - 1) / BMg);
        gemm_mma_kernel<false, false><<<grid, 256, SMEM_BYTES>>>(
            hid_ptr, W2, b2, out, N, D_FF, D_OUT);
    }
}